// round 4
// baseline (speedup 1.0000x reference)
#include <cuda_runtime.h>

#define HDIM 1024
#define LSEQ 512
#define G4   4096      // 4*H gate rows
#define KIN  4096      // input feature dim (2H + 2H)
#define NLAB 122
#define RGRID 128      // recurrent kernel CTAs (<=148: one wave, persistent-safe)

typedef unsigned long long u64;

// ---------------- packed f32x2 helpers (FFMA2 path, sm_103a) ------------------
__device__ __forceinline__ u64 pack2(float lo, float hi) {
    u64 r; asm("mov.b64 %0, {%1, %2};" : "=l"(r) : "f"(lo), "f"(hi)); return r;
}
__device__ __forceinline__ void unpack2(u64 v, float& lo, float& hi) {
    asm("mov.b64 {%0, %1}, %2;" : "=f"(lo), "=f"(hi) : "l"(v));
}
__device__ __forceinline__ u64 fma2(u64 a, u64 b, u64 c) {
    u64 d; asm("fma.rn.f32x2 %0, %1, %2, %3;" : "=l"(d) : "l"(a), "l"(b), "l"(c));
    return d;
}

// ---------------- scratch (no allocation allowed; device globals) -------------
__device__ __align__(256) float g_Wcomb[G4 * HDIM];   // W_ih[:,4096:] + W_hh
__device__ __align__(256) float g_bias[G4];           // b_ih + b_hh
__device__ __align__(256) float g_Xpre[LSEQ * G4];    // input projection + bias
__device__ __align__(256) float g_outs[LSEQ * HDIM];  // h_t for all steps
__device__ __align__(256) int   g_flags[RGRID];       // per-CTA step flags

// ---------------- prep: fold recurrent weights & biases, reset flags ----------
__global__ void prep_kernel(const float* __restrict__ W_ih,
                            const float* __restrict__ W_hh,
                            const float* __restrict__ b_ih,
                            const float* __restrict__ b_hh) {
    int idx = blockIdx.x * blockDim.x + threadIdx.x;
    if (idx < G4 * HDIM) {
        int r = idx >> 10;           // gate row
        int c = idx & 1023;          // h col
        g_Wcomb[idx] = W_ih[(size_t)r * 5120 + 4096 + c] + W_hh[idx];
    }
    if (idx < G4) g_bias[idx] = b_ih[idx] + b_hh[idx];
    if (idx < RGRID) g_flags[idx] = 0;
}

// ---------------- pregemm: Xpre[t][r] = bias[r] + W_ih[r, :4096] . feats[t] ---
#define BM 128
#define BN 128
#define BK 16
#define TM 8
#define TN 8

__global__ __launch_bounds__(256) void pregemm_kernel(
    const float* __restrict__ x, const float* __restrict__ hi,
    const float* __restrict__ W_ih) {
    __shared__ __align__(16) float As[BK][BM + 4];   // [k][m]  (m = timestep)
    __shared__ __align__(16) float Bs[BK][BN + 4];   // [k][n]  (n = gate row)

    const int bm = blockIdx.x * BM;
    const int bn = blockIdx.y * BN;
    const int tid = threadIdx.x;
    const int tr = tid / 16;
    const int tc = tid % 16;

    u64 acc2[TM / 2][TN];            // packed over the m (i) dimension
#pragma unroll
    for (int i = 0; i < TM / 2; i++)
#pragma unroll
        for (int j = 0; j < TN; j++) acc2[i][j] = pack2(0.f, 0.f);

    for (int k0 = 0; k0 < KIN; k0 += BK) {
        // A tile: 128 rows x 16 floats = 512 float4, 256 threads -> 2 each.
#pragma unroll
        for (int it = 0; it < 2; it++) {
            int idx = tid + it * 256;
            int m = idx >> 2;
            int kq = idx & 3;
            int gk = k0 + kq * 4;
            float4 v;
            if (gk < 2048)
                v = *(const float4*)(x + (size_t)(bm + m) * 2048 + gk);
            else
                v = *(const float4*)(hi + (size_t)(bm + m) * 2048 + gk - 2048);
            As[kq * 4 + 0][m] = v.x;
            As[kq * 4 + 1][m] = v.y;
            As[kq * 4 + 2][m] = v.z;
            As[kq * 4 + 3][m] = v.w;
        }
#pragma unroll
        for (int it = 0; it < 2; it++) {
            int idx = tid + it * 256;
            int n = idx >> 2;
            int kq = idx & 3;
            float4 v = *(const float4*)(W_ih + (size_t)(bn + n) * 5120 + k0 + kq * 4);
            Bs[kq * 4 + 0][n] = v.x;
            Bs[kq * 4 + 1][n] = v.y;
            Bs[kq * 4 + 2][n] = v.z;
            Bs[kq * 4 + 3][n] = v.w;
        }
        __syncthreads();
#pragma unroll
        for (int k = 0; k < BK; k++) {
            u64 a2[TM / 2], b2[TN];
#pragma unroll
            for (int i = 0; i < TM / 2; i++)
                a2[i] = *(const u64*)&As[k][tr * TM + 2 * i];
#pragma unroll
            for (int j = 0; j < TN; j++) {
                float bv = Bs[k][tc * TN + j];
                b2[j] = pack2(bv, bv);
            }
#pragma unroll
            for (int i = 0; i < TM / 2; i++)
#pragma unroll
                for (int j = 0; j < TN; j++)
                    acc2[i][j] = fma2(a2[i], b2[j], acc2[i][j]);
        }
        __syncthreads();
    }
#pragma unroll
    for (int i = 0; i < TM / 2; i++) {
#pragma unroll
        for (int j = 0; j < TN; j++) {
            int n = bn + tc * TN + j;
            float lo, hh;
            unpack2(acc2[i][j], lo, hh);
            int m0 = bm + tr * TM + 2 * i;
            float bb = g_bias[n];
            g_Xpre[(size_t)m0 * G4 + n]       = lo + bb;
            g_Xpre[(size_t)(m0 + 1) * G4 + n] = hh + bb;
        }
    }
}

// ---------------- recurrent persistent kernel --------------------------------
__device__ __forceinline__ float fast_sigmoid(float v) {
    return 1.f / (1.f + __expf(-v));
}
__device__ __forceinline__ float fast_tanh(float v) {
    v = fminf(fmaxf(v, -15.f), 15.f);
    float e = __expf(-2.f * v);
    return (1.f - e) / (1.f + e);
}

__global__ __launch_bounds__(256, 1) void recur_kernel() {
    __shared__ __align__(16) float h_s[HDIM];
    const int tid  = threadIdx.x;
    const int lane = tid & 31;
    const int warp = tid >> 5;                 // 0..7
    const int j    = blockIdx.x * 8 + warp;    // h element, 0..1023

    // This warp's 4 gate rows of W_comb live in registers, packed f32x2.
    // Lane handles col pairs {p*64 + 2*lane, +1}, p = 0..15.
    u64 w2[4][16];
#pragma unroll
    for (int g = 0; g < 4; g++) {
        const u64* base = (const u64*)(g_Wcomb + (size_t)(j + g * HDIM) * HDIM);
#pragma unroll
        for (int p = 0; p < 16; p++) w2[g][p] = base[p * 32 + lane];
    }

    float c_state = 0.f;    // meaningful on lane 0 only

    for (int t = 0; t < LSEQ; t++) {
        // Prefetch the precomputed gate terms (off the h critical path)
        float xi = 0.f, xf = 0.f, xg = 0.f, xo = 0.f;
        if (lane == 0) {
            const float* xp = g_Xpre + (size_t)t * G4;
            xi = __ldg(xp + j);
            xf = __ldg(xp + j + 1024);
            xg = __ldg(xp + j + 2048);
            xo = __ldg(xp + j + 3072);
        }

        // Stage h_{t-1} into shared (h_{-1} = 0). Bypass L1 for cross-CTA data.
        if (t == 0) {
            ((float4*)h_s)[tid] = make_float4(0.f, 0.f, 0.f, 0.f);
        } else {
            const float4* hp4 = (const float4*)(g_outs + (size_t)(t - 1) * HDIM);
            ((float4*)h_s)[tid] = __ldcg(hp4 + tid);
        }
        __syncthreads();

        u64 acc0 = pack2(0.f, 0.f), acc1 = acc0, acc2v = acc0, acc3 = acc0;
        const u64* h2 = (const u64*)h_s;
#pragma unroll
        for (int p = 0; p < 16; p++) {
            u64 hv = h2[p * 32 + lane];
            acc0 = fma2(w2[0][p], hv, acc0);
            acc1 = fma2(w2[1][p], hv, acc1);
            acc2v = fma2(w2[2][p], hv, acc2v);
            acc3 = fma2(w2[3][p], hv, acc3);
        }
        float l0, h0, l1, h1, l2, hh2, l3, h3;
        unpack2(acc0, l0, h0);
        unpack2(acc1, l1, h1);
        unpack2(acc2v, l2, hh2);
        unpack2(acc3, l3, h3);
        float a0 = l0 + h0, a1 = l1 + h1, a2 = l2 + hh2, a3 = l3 + h3;
#pragma unroll
        for (int off = 16; off > 0; off >>= 1) {
            a0 += __shfl_down_sync(0xffffffffu, a0, off);
            a1 += __shfl_down_sync(0xffffffffu, a1, off);
            a2 += __shfl_down_sync(0xffffffffu, a2, off);
            a3 += __shfl_down_sync(0xffffffffu, a3, off);
        }
        if (lane == 0) {
            float gi = xi + a0;
            float gf = xf + a1;
            float gg = xg + a2;
            float go = xo + a3;
            float si = fast_sigmoid(gi);
            float sf = fast_sigmoid(gf);
            float so = fast_sigmoid(go);
            c_state = sf * c_state + si * fast_tanh(gg);
            g_outs[(size_t)t * HDIM + j] = so * fast_tanh(c_state);
        }
        __syncthreads();   // h stores done CTA-wide before the release store

        if (t < LSEQ - 1) {
            // Release: one plain release-store per CTA (no RMW serialization).
            if (tid == 0) {
                asm volatile("st.release.gpu.u32 [%0], %1;"
                             :: "l"(&g_flags[blockIdx.x]), "r"(t + 1) : "memory");
            }
            // Acquire: 128 threads each poll one CTA's flag.
            if (tid < RGRID) {
                int v;
                do {
                    asm volatile("ld.acquire.gpu.u32 %0, [%1];"
                                 : "=r"(v) : "l"(&g_flags[tid]) : "memory");
                } while (v < t + 1);
            }
            __syncthreads();
        }
    }
}

// ---------------- final FC: out[t][l] = b_fc[l] + outs[t] . W_fc[l] ----------
// 4 timesteps per block, 256 threads: half-block per timestep pair.
__global__ __launch_bounds__(256) void fc_kernel(const float* __restrict__ W_fc,
                                                 const float* __restrict__ b_fc,
                                                 float* __restrict__ out) {
    __shared__ __align__(16) float hs[4][HDIM];
    const int t0  = blockIdx.x * 4;
    const int tid = threadIdx.x;
    const int half = tid >> 7;          // 0 or 1
    const int l    = tid & 127;         // label index

    const float4* src = (const float4*)(g_outs + (size_t)t0 * HDIM);
    float4* dst = (float4*)hs;
#pragma unroll
    for (int i = tid; i < HDIM; i += 256) dst[i] = src[i];   // 1024 float4
    __syncthreads();

    if (l < NLAB) {
        const float4* wr = (const float4*)(W_fc + (size_t)l * HDIM);
        const float4* ha = (const float4*)hs[half * 2];
        const float4* hb = (const float4*)hs[half * 2 + 1];
        float s0 = 0.f, s1 = 0.f;
#pragma unroll 8
        for (int k = 0; k < HDIM / 4; k++) {
            float4 w = wr[k];
            float4 a = ha[k], b = hb[k];
            s0 += w.x * a.x + w.y * a.y + w.z * a.z + w.w * a.w;
            s1 += w.x * b.x + w.y * b.y + w.z * b.z + w.w * b.w;
        }
        float bb = b_fc[l];
        out[(size_t)(t0 + half * 2) * NLAB + l]     = s0 + bb;
        out[(size_t)(t0 + half * 2 + 1) * NLAB + l] = s1 + bb;
    }
}

// ---------------- launch ------------------------------------------------------
extern "C" void kernel_launch(void* const* d_in, const int* in_sizes, int n_in,
                              void* d_out, int out_size) {
    const float* x    = (const float*)d_in[0];
    const float* hi   = (const float*)d_in[1];
    const float* W_ih = (const float*)d_in[2];
    const float* W_hh = (const float*)d_in[3];
    const float* b_ih = (const float*)d_in[4];
    const float* b_hh = (const float*)d_in[5];
    const float* W_fc = (const float*)d_in[6];
    const float* b_fc = (const float*)d_in[7];
    float* out = (float*)d_out;

    prep_kernel<<<(G4 * HDIM + 255) / 256, 256>>>(W_ih, W_hh, b_ih, b_hh);

    dim3 pgrid(LSEQ / BM, G4 / BN);   // (4, 32)
    pregemm_kernel<<<pgrid, 256>>>(x, hi, W_ih);

    recur_kernel<<<RGRID, 256>>>();

    fc_kernel<<<LSEQ / 4, 256>>>(W_fc, b_fc, out);
}

// round 5
// speedup vs baseline: 2.1263x; 2.1263x over previous
#include <cuda_runtime.h>

#define HDIM 1024
#define LSEQ 512
#define G4   4096      // 4*H gate rows
#define KIN  4096      // input feature dim (2H + 2H)
#define NLAB 122
#define RGRID 128      // recurrent kernel CTAs (<=148: one wave, persistent-safe)

#define SENTINEL 0x7FC00001u   // NaN payload; computed h (= sig*tanh) is never NaN

// ---------------- scratch (no allocation allowed; device globals) -------------
__device__ __align__(256) float g_Wcomb[G4 * HDIM];   // W_ih[:,4096:] + W_hh
__device__ __align__(256) float g_bias[G4];           // b_ih + b_hh
__device__ __align__(256) float g_Xpre[LSEQ * G4];    // input projection + bias
__device__ __align__(256) float g_outs[LSEQ * HDIM];  // h_t for all steps

// ---------------- L2-coherent load/store helpers ------------------------------
__device__ __forceinline__ float4 ldcg4(const float4* p) {
    float4 v;
    asm volatile("ld.global.cg.v4.f32 {%0,%1,%2,%3}, [%4];"
                 : "=f"(v.x), "=f"(v.y), "=f"(v.z), "=f"(v.w) : "l"(p));
    return v;
}
__device__ __forceinline__ void stcg(float* p, float v) {
    asm volatile("st.global.cg.f32 [%0], %1;" :: "l"(p), "f"(v));
}
__device__ __forceinline__ bool has_sentinel(float4 v) {
    return (__float_as_uint(v.x) == SENTINEL) | (__float_as_uint(v.y) == SENTINEL) |
           (__float_as_uint(v.z) == SENTINEL) | (__float_as_uint(v.w) == SENTINEL);
}

// ---------------- prep: fold weights/biases, poison h buffer ------------------
__global__ void prep_kernel(const float* __restrict__ W_ih,
                            const float* __restrict__ W_hh,
                            const float* __restrict__ b_ih,
                            const float* __restrict__ b_hh) {
    int idx = blockIdx.x * blockDim.x + threadIdx.x;
    if (idx < G4 * HDIM) {
        int r = idx >> 10;           // gate row
        int c = idx & 1023;          // h col
        g_Wcomb[idx] = W_ih[(size_t)r * 5120 + 4096 + c] + W_hh[idx];
    }
    if (idx < G4) g_bias[idx] = b_ih[idx] + b_hh[idx];
    if (idx < LSEQ * HDIM) g_outs[idx] = __uint_as_float(SENTINEL);
}

// ---------------- pregemm: Xpre[t][r] = bias[r] + W_ih[r, :4096] . feats[t] ---
#define BM 128
#define BN 128
#define BK 16
#define TM 8
#define TN 8

__global__ __launch_bounds__(256) void pregemm_kernel(
    const float* __restrict__ x, const float* __restrict__ hi,
    const float* __restrict__ W_ih) {
    __shared__ __align__(16) float As[BK][BM + 4];   // [k][m]  (m = timestep)
    __shared__ __align__(16) float Bs[BK][BN + 4];   // [k][n]  (n = gate row)

    const int bm = blockIdx.x * BM;
    const int bn = blockIdx.y * BN;
    const int tid = threadIdx.x;
    const int tr = tid / 16;
    const int tc = tid % 16;

    float acc[TM][TN];
#pragma unroll
    for (int i = 0; i < TM; i++)
#pragma unroll
        for (int j = 0; j < TN; j++) acc[i][j] = 0.f;

    for (int k0 = 0; k0 < KIN; k0 += BK) {
        // A tile: 128 rows x 16 floats = 512 float4, 256 threads -> 2 each.
        // A float4 never straddles the x/hi boundary (2048 % 16 == 0).
#pragma unroll
        for (int it = 0; it < 2; it++) {
            int idx = tid + it * 256;
            int m = idx >> 2;
            int kq = idx & 3;
            int gk = k0 + kq * 4;
            float4 v;
            if (gk < 2048)
                v = *(const float4*)(x + (size_t)(bm + m) * 2048 + gk);
            else
                v = *(const float4*)(hi + (size_t)(bm + m) * 2048 + gk - 2048);
            As[kq * 4 + 0][m] = v.x;
            As[kq * 4 + 1][m] = v.y;
            As[kq * 4 + 2][m] = v.z;
            As[kq * 4 + 3][m] = v.w;
        }
#pragma unroll
        for (int it = 0; it < 2; it++) {
            int idx = tid + it * 256;
            int n = idx >> 2;
            int kq = idx & 3;
            float4 v = *(const float4*)(W_ih + (size_t)(bn + n) * 5120 + k0 + kq * 4);
            Bs[kq * 4 + 0][n] = v.x;
            Bs[kq * 4 + 1][n] = v.y;
            Bs[kq * 4 + 2][n] = v.z;
            Bs[kq * 4 + 3][n] = v.w;
        }
        __syncthreads();
#pragma unroll
        for (int k = 0; k < BK; k++) {
            float a[TM], b[TN];
#pragma unroll
            for (int i = 0; i < TM; i++) a[i] = As[k][tr * TM + i];
#pragma unroll
            for (int j = 0; j < TN; j++) b[j] = Bs[k][tc * TN + j];
#pragma unroll
            for (int i = 0; i < TM; i++)
#pragma unroll
                for (int j = 0; j < TN; j++) acc[i][j] += a[i] * b[j];
        }
        __syncthreads();
    }
#pragma unroll
    for (int i = 0; i < TM; i++) {
        int m = bm + tr * TM + i;
#pragma unroll
        for (int j = 0; j < TN; j++) {
            int n = bn + tc * TN + j;
            g_Xpre[(size_t)m * G4 + n] = acc[i][j] + g_bias[n];
        }
    }
}

// ---------------- recurrent persistent kernel --------------------------------
// Synchronization is data-driven: g_outs is poisoned with SENTINEL; consumers
// poll h values directly. The producing st.global.cg IS the release; no flags,
// no atomics, no fences, no grid barrier.
__device__ __forceinline__ float fast_sigmoid(float v) {
    return 1.f / (1.f + __expf(-v));
}
__device__ __forceinline__ float fast_tanh(float v) {
    v = fminf(fmaxf(v, -15.f), 15.f);
    float e = __expf(-2.f * v);
    return (1.f - e) / (1.f + e);
}

__global__ __launch_bounds__(256, 1) void recur_kernel() {
    __shared__ __align__(16) float h_s[HDIM];
    const int tid  = threadIdx.x;
    const int lane = tid & 31;
    const int warp = tid >> 5;                 // 0..7
    const int j    = blockIdx.x * 8 + warp;    // h element, 0..1023

    // This warp's 4 gate rows of W_comb live in registers.
    // Lane handles cols {lane, lane+32, ..., lane+992}.
    float w[4][32];
#pragma unroll
    for (int g = 0; g < 4; g++) {
        const float* base = g_Wcomb + (size_t)(j + g * HDIM) * HDIM;
#pragma unroll
        for (int k = 0; k < 32; k++) w[g][k] = base[k * 32 + lane];
    }

    float c_state = 0.f;    // meaningful on lane 0 only

    for (int t = 0; t < LSEQ; t++) {
        // Prefetch precomputed gate terms (off the h critical path)
        float xi = 0.f, xf = 0.f, xg = 0.f, xo = 0.f;
        if (lane == 0) {
            const float* xp = g_Xpre + (size_t)t * G4;
            xi = __ldg(xp + j);
            xf = __ldg(xp + j + 1024);
            xg = __ldg(xp + j + 2048);
            xo = __ldg(xp + j + 3072);
        }

        // Stage h_{t-1}: poll the values themselves until non-sentinel.
        if (t == 0) {
            ((float4*)h_s)[tid] = make_float4(0.f, 0.f, 0.f, 0.f);
        } else {
            const float4* hp4 = (const float4*)(g_outs + (size_t)(t - 1) * HDIM);
            float4 v = ldcg4(hp4 + tid);
            while (has_sentinel(v)) {
                __nanosleep(64);
                v = ldcg4(hp4 + tid);
            }
            ((float4*)h_s)[tid] = v;
        }
        __syncthreads();

        float a0 = 0.f, a1 = 0.f, a2 = 0.f, a3 = 0.f;
#pragma unroll
        for (int k = 0; k < 32; k++) {
            float hv = h_s[k * 32 + lane];
            a0 += w[0][k] * hv;
            a1 += w[1][k] * hv;
            a2 += w[2][k] * hv;
            a3 += w[3][k] * hv;
        }
#pragma unroll
        for (int off = 16; off > 0; off >>= 1) {
            a0 += __shfl_down_sync(0xffffffffu, a0, off);
            a1 += __shfl_down_sync(0xffffffffu, a1, off);
            a2 += __shfl_down_sync(0xffffffffu, a2, off);
            a3 += __shfl_down_sync(0xffffffffu, a3, off);
        }
        if (lane == 0) {
            float gi = xi + a0;
            float gf = xf + a1;
            float gg = xg + a2;
            float go = xo + a3;
            float si = fast_sigmoid(gi);
            float sf = fast_sigmoid(gf);
            float so = fast_sigmoid(go);
            c_state = sf * c_state + si * fast_tanh(gg);
            // This store is the release: consumers poll this exact location.
            stcg(g_outs + (size_t)t * HDIM + j, so * fast_tanh(c_state));
        }
        __syncthreads();   // protect h_s reuse next iteration
    }
}

// ---------------- final FC: out[t][l] = b_fc[l] + outs[t] . W_fc[l] ----------
// 4 timesteps per block, 256 threads: half-block per timestep pair.
__global__ __launch_bounds__(256) void fc_kernel(const float* __restrict__ W_fc,
                                                 const float* __restrict__ b_fc,
                                                 float* __restrict__ out) {
    __shared__ __align__(16) float hs[4][HDIM];
    const int t0  = blockIdx.x * 4;
    const int tid = threadIdx.x;
    const int half = tid >> 7;          // 0 or 1
    const int l    = tid & 127;         // label index

    const float4* src = (const float4*)(g_outs + (size_t)t0 * HDIM);
    float4* dst = (float4*)hs;
#pragma unroll
    for (int i = tid; i < HDIM; i += 256) dst[i] = src[i];   // 1024 float4
    __syncthreads();

    if (l < NLAB) {
        const float4* wr = (const float4*)(W_fc + (size_t)l * HDIM);
        const float4* ha = (const float4*)hs[half * 2];
        const float4* hb = (const float4*)hs[half * 2 + 1];
        float s0 = 0.f, s1 = 0.f;
#pragma unroll 8
        for (int k = 0; k < HDIM / 4; k++) {
            float4 w = wr[k];
            float4 a = ha[k], b = hb[k];
            s0 += w.x * a.x + w.y * a.y + w.z * a.z + w.w * a.w;
            s1 += w.x * b.x + w.y * b.y + w.z * b.z + w.w * b.w;
        }
        float bb = b_fc[l];
        out[(size_t)(t0 + half * 2) * NLAB + l]     = s0 + bb;
        out[(size_t)(t0 + half * 2 + 1) * NLAB + l] = s1 + bb;
    }
}

// ---------------- launch ------------------------------------------------------
extern "C" void kernel_launch(void* const* d_in, const int* in_sizes, int n_in,
                              void* d_out, int out_size) {
    const float* x    = (const float*)d_in[0];
    const float* hi   = (const float*)d_in[1];
    const float* W_ih = (const float*)d_in[2];
    const float* W_hh = (const float*)d_in[3];
    const float* b_ih = (const float*)d_in[4];
    const float* b_hh = (const float*)d_in[5];
    const float* W_fc = (const float*)d_in[6];
    const float* b_fc = (const float*)d_in[7];
    float* out = (float*)d_out;

    prep_kernel<<<(G4 * HDIM + 255) / 256, 256>>>(W_ih, W_hh, b_ih, b_hh);

    dim3 pgrid(LSEQ / BM, G4 / BN);   // (4, 32)
    pregemm_kernel<<<pgrid, 256>>>(x, hi, W_ih);

    recur_kernel<<<RGRID, 256>>>();

    fc_kernel<<<LSEQ / 4, 256>>>(W_fc, b_fc, out);
}

// round 6
// speedup vs baseline: 2.4419x; 1.1484x over previous
#include <cuda_runtime.h>

#define HDIM 1024
#define LSEQ 512
#define G4   4096      // 4*H gate rows
#define KIN  4096      // input feature dim (2H + 2H)
#define NLAB 122
#define RGRID 128      // recurrent kernel CTAs (<=148: one wave, persistent-safe)

#define SENTINEL 0x7FC00001u   // NaN payload; computed values are never NaN

// ---------------- scratch (no allocation allowed; device globals) -------------
__device__ __align__(256) float g_Wcomb[G4 * HDIM];   // W_ih[:,4096:] + W_hh
__device__ __align__(256) float g_bias[G4];           // b_ih + b_hh
__device__ __align__(256) float g_Xpre[LSEQ * G4];    // input projection + bias
__device__ __align__(256) float g_outs[LSEQ * HDIM];  // h_t for all steps

// ---------------- L2-coherent load/store helpers ------------------------------
__device__ __forceinline__ float4 ldcg4(const float4* p) {
    float4 v;
    asm volatile("ld.global.cg.v4.f32 {%0,%1,%2,%3}, [%4];"
                 : "=f"(v.x), "=f"(v.y), "=f"(v.z), "=f"(v.w) : "l"(p));
    return v;
}
__device__ __forceinline__ float ldcg1(const float* p) {
    float v;
    asm volatile("ld.global.cg.f32 %0, [%1];" : "=f"(v) : "l"(p));
    return v;
}
__device__ __forceinline__ void stcg(float* p, float v) {
    asm volatile("st.global.cg.f32 [%0], %1;" :: "l"(p), "f"(v));
}
__device__ __forceinline__ bool has_sentinel(float4 v) {
    return (__float_as_uint(v.x) == SENTINEL) | (__float_as_uint(v.y) == SENTINEL) |
           (__float_as_uint(v.z) == SENTINEL) | (__float_as_uint(v.w) == SENTINEL);
}
__device__ __forceinline__ float poll_scalar(const float* p) {
    float v = ldcg1(p);
    while (__float_as_uint(v) == SENTINEL) { __nanosleep(64); v = ldcg1(p); }
    return v;
}

// ---------------- prep: fold weights/biases, poison Xpre + h buffers ----------
__global__ void prep_kernel(const float* __restrict__ W_ih,
                            const float* __restrict__ W_hh,
                            const float* __restrict__ b_ih,
                            const float* __restrict__ b_hh) {
    int idx = blockIdx.x * blockDim.x + threadIdx.x;
    if (idx < G4 * HDIM) {
        int r = idx >> 10;           // gate row
        int c = idx & 1023;          // h col
        g_Wcomb[idx] = W_ih[(size_t)r * 5120 + 4096 + c] + W_hh[idx];
    }
    if (idx < G4) g_bias[idx] = b_ih[idx] + b_hh[idx];
    if (idx < LSEQ * G4)  g_Xpre[idx] = __uint_as_float(SENTINEL);
    if (idx < LSEQ * HDIM) g_outs[idx] = __uint_as_float(SENTINEL);
}

// ---------------- pregemm (concurrent with recur): 64x64x16 tiles -------------
// Xpre[t][r] = bias[r] + W_ih[r, :4096] . feats[t].  Slim CTA (128 thr, ~70
// regs, 9KB smem) so it co-resides with a recur CTA on every SM and fills the
// recurrence's idle issue slots. grid=(64 n-strips, 8 t-blocks): t-block-major
// bid order => Xpre rows for early timesteps finish first.
__global__ __launch_bounds__(128) void pregemm_kernel(
    const float* __restrict__ x, const float* __restrict__ hi,
    const float* __restrict__ W_ih) {
    __shared__ __align__(16) float As[16][68];   // [k][t]
    __shared__ __align__(16) float Bs[16][68];   // [k][n]

    const int bn = blockIdx.x * 64;   // gate-row strip
    const int bt = blockIdx.y * 64;   // timestep block
    const int tid = threadIdx.x;
    const int tm = tid & 15;          // 16 m-groups of 4 rows
    const int tn = tid >> 4;          // 8 n-groups of 8 cols

    float acc[4][8];
#pragma unroll
    for (int i = 0; i < 4; i++)
#pragma unroll
        for (int j = 0; j < 8; j++) acc[i][j] = 0.f;

    for (int k0 = 0; k0 < KIN; k0 += 16) {
        // A tile: 64 t-rows x 16 k = 256 float4, 128 thr -> 2 each.
        // float4 never straddles the x/hi boundary (2048 % 16 == 0).
#pragma unroll
        for (int it = 0; it < 2; it++) {
            int idx = tid + it * 128;
            int m = idx >> 2;
            int kq = idx & 3;
            int gk = k0 + kq * 4;
            float4 v;
            if (gk < 2048)
                v = *(const float4*)(x + (size_t)(bt + m) * 2048 + gk);
            else
                v = *(const float4*)(hi + (size_t)(bt + m) * 2048 + gk - 2048);
            As[kq * 4 + 0][m] = v.x;
            As[kq * 4 + 1][m] = v.y;
            As[kq * 4 + 2][m] = v.z;
            As[kq * 4 + 3][m] = v.w;
        }
        // B tile: 64 gate rows x 16 k (W_ih row stride 5120 floats)
#pragma unroll
        for (int it = 0; it < 2; it++) {
            int idx = tid + it * 128;
            int n = idx >> 2;
            int kq = idx & 3;
            float4 v = *(const float4*)(W_ih + (size_t)(bn + n) * 5120 + k0 + kq * 4);
            Bs[kq * 4 + 0][n] = v.x;
            Bs[kq * 4 + 1][n] = v.y;
            Bs[kq * 4 + 2][n] = v.z;
            Bs[kq * 4 + 3][n] = v.w;
        }
        __syncthreads();
#pragma unroll
        for (int k = 0; k < 16; k++) {
            float4 a4 = *(const float4*)&As[k][tm * 4];
            float4 b0 = *(const float4*)&Bs[k][tn * 8];
            float4 b1 = *(const float4*)&Bs[k][tn * 8 + 4];
            float a[4] = {a4.x, a4.y, a4.z, a4.w};
            float b[8] = {b0.x, b0.y, b0.z, b0.w, b1.x, b1.y, b1.z, b1.w};
#pragma unroll
            for (int i = 0; i < 4; i++)
#pragma unroll
                for (int j = 0; j < 8; j++) acc[i][j] += a[i] * b[j];
        }
        __syncthreads();
    }
    // Epilogue: add bias, st.cg so the polling recur CTAs see values in L2.
#pragma unroll
    for (int j = 0; j < 8; j++) {
        int n = bn + tn * 8 + j;
        float bb = g_bias[n];
#pragma unroll
        for (int i = 0; i < 4; i++) {
            int m = bt + tm * 4 + i;
            stcg(g_Xpre + (size_t)m * G4 + n, acc[i][j] + bb);
        }
    }
}

// ---------------- recurrent persistent kernel --------------------------------
// Data-driven sync: both g_Xpre (produced by the concurrent pregemm) and
// g_outs (produced by peer CTAs) are sentinel-poisoned and polled directly.
__device__ __forceinline__ float fast_sigmoid(float v) {
    return 1.f / (1.f + __expf(-v));
}
__device__ __forceinline__ float fast_tanh(float v) {
    v = fminf(fmaxf(v, -15.f), 15.f);
    float e = __expf(-2.f * v);
    return (1.f - e) / (1.f + e);
}

__global__ __launch_bounds__(256, 1) void recur_kernel() {
    __shared__ __align__(16) float h_s[HDIM];
    const int tid  = threadIdx.x;
    const int lane = tid & 31;
    const int warp = tid >> 5;                 // 0..7
    const int j    = blockIdx.x * 8 + warp;    // h element, 0..1023

    // This warp's 4 gate rows of W_comb live in registers.
    // Lane handles cols {lane, lane+32, ..., lane+992}.
    float w[4][32];
#pragma unroll
    for (int g = 0; g < 4; g++) {
        const float* base = g_Wcomb + (size_t)(j + g * HDIM) * HDIM;
#pragma unroll
        for (int k = 0; k < 32; k++) w[g][k] = base[k * 32 + lane];
    }

    float c_state = 0.f;    // meaningful on lane 0 only

    for (int t = 0; t < LSEQ; t++) {
        // Gate pre-activations from the concurrent pregemm: poll until real.
        float xi = 0.f, xf = 0.f, xg = 0.f, xo = 0.f;
        if (lane == 0) {
            const float* xp = g_Xpre + (size_t)t * G4;
            xi = poll_scalar(xp + j);
            xf = poll_scalar(xp + j + 1024);
            xg = poll_scalar(xp + j + 2048);
            xo = poll_scalar(xp + j + 3072);
        }

        // Stage h_{t-1}: poll the values themselves until non-sentinel.
        if (t == 0) {
            ((float4*)h_s)[tid] = make_float4(0.f, 0.f, 0.f, 0.f);
        } else {
            const float4* hp4 = (const float4*)(g_outs + (size_t)(t - 1) * HDIM);
            float4 v = ldcg4(hp4 + tid);
            while (has_sentinel(v)) {
                __nanosleep(64);
                v = ldcg4(hp4 + tid);
            }
            ((float4*)h_s)[tid] = v;
        }
        __syncthreads();

        float a0 = 0.f, a1 = 0.f, a2 = 0.f, a3 = 0.f;
#pragma unroll
        for (int k = 0; k < 32; k++) {
            float hv = h_s[k * 32 + lane];
            a0 += w[0][k] * hv;
            a1 += w[1][k] * hv;
            a2 += w[2][k] * hv;
            a3 += w[3][k] * hv;
        }
#pragma unroll
        for (int off = 16; off > 0; off >>= 1) {
            a0 += __shfl_down_sync(0xffffffffu, a0, off);
            a1 += __shfl_down_sync(0xffffffffu, a1, off);
            a2 += __shfl_down_sync(0xffffffffu, a2, off);
            a3 += __shfl_down_sync(0xffffffffu, a3, off);
        }
        if (lane == 0) {
            float gi = xi + a0;
            float gf = xf + a1;
            float gg = xg + a2;
            float go = xo + a3;
            float si = fast_sigmoid(gi);
            float sf = fast_sigmoid(gf);
            float so = fast_sigmoid(go);
            c_state = sf * c_state + si * fast_tanh(gg);
            // This store is the release: consumers poll this exact location.
            stcg(g_outs + (size_t)t * HDIM + j, so * fast_tanh(c_state));
        }
        __syncthreads();   // protect h_s reuse next iteration
    }
}

// ---------------- final FC: out[t][l] = b_fc[l] + outs[t] . W_fc[l] ----------
__global__ __launch_bounds__(256) void fc_kernel(const float* __restrict__ W_fc,
                                                 const float* __restrict__ b_fc,
                                                 float* __restrict__ out) {
    __shared__ __align__(16) float hs[4][HDIM];
    const int t0  = blockIdx.x * 4;
    const int tid = threadIdx.x;
    const int half = tid >> 7;          // 0 or 1
    const int l    = tid & 127;         // label index

    const float4* src = (const float4*)(g_outs + (size_t)t0 * HDIM);
    float4* dst = (float4*)hs;
#pragma unroll
    for (int i = tid; i < HDIM; i += 256) dst[i] = src[i];   // 1024 float4
    __syncthreads();

    if (l < NLAB) {
        const float4* wr = (const float4*)(W_fc + (size_t)l * HDIM);
        const float4* ha = (const float4*)hs[half * 2];
        const float4* hb = (const float4*)hs[half * 2 + 1];
        float s0 = 0.f, s1 = 0.f;
#pragma unroll 8
        for (int k = 0; k < HDIM / 4; k++) {
            float4 w = wr[k];
            float4 a = ha[k], b = hb[k];
            s0 += w.x * a.x + w.y * a.y + w.z * a.z + w.w * a.w;
            s1 += w.x * b.x + w.y * b.y + w.z * b.z + w.w * b.w;
        }
        float bb = b_fc[l];
        out[(size_t)(t0 + half * 2) * NLAB + l]     = s0 + bb;
        out[(size_t)(t0 + half * 2 + 1) * NLAB + l] = s1 + bb;
    }
}

// ---------------- launch ------------------------------------------------------
// Multi-stream fork so pregemm runs CONCURRENTLY with the latency-bound
// recurrence (standard cross-stream capture via events). Stream/events are
// created once on the first (non-captured correctness) call; the captured GPU
// work is identical on every call.
extern "C" void kernel_launch(void* const* d_in, const int* in_sizes, int n_in,
                              void* d_out, int out_size) {
    const float* x    = (const float*)d_in[0];
    const float* hi   = (const float*)d_in[1];
    const float* W_ih = (const float*)d_in[2];
    const float* W_hh = (const float*)d_in[3];
    const float* b_ih = (const float*)d_in[4];
    const float* b_hh = (const float*)d_in[5];
    const float* W_fc = (const float*)d_in[6];
    const float* b_fc = (const float*)d_in[7];
    float* out = (float*)d_out;

    static cudaStream_t s2 = nullptr;
    static cudaEvent_t evA = nullptr, evB = nullptr;
    if (s2 == nullptr) {
        cudaStreamCreateWithFlags(&s2, cudaStreamNonBlocking);
        cudaEventCreateWithFlags(&evA, cudaEventDisableTiming);
        cudaEventCreateWithFlags(&evB, cudaEventDisableTiming);
    }

    prep_kernel<<<(G4 * HDIM + 255) / 256, 256>>>(W_ih, W_hh, b_ih, b_hh);

    // Fork: pregemm on s2 depends on prep; recur continues on the main stream.
    cudaEventRecord(evA, 0);
    cudaStreamWaitEvent(s2, evA, 0);

    dim3 pgrid(64, 8);   // 64 n-strips x 8 t-blocks; t-block-major bid order
    pregemm_kernel<<<pgrid, 128, 0, s2>>>(x, hi, W_ih);
    cudaEventRecord(evB, s2);

    recur_kernel<<<RGRID, 256>>>();

    // Join before fc (fc only reads g_outs, but the graph must re-converge).
    cudaStreamWaitEvent(0, evB, 0);
    fc_kernel<<<LSEQ / 4, 256>>>(W_fc, b_fc, out);
}